// round 3
// baseline (speedup 1.0000x reference)
#include <cuda_runtime.h>
#include <cuda_bf16.h>

#define NMAX 512
#define DDIM 128
#define TA 4
#define MARGIN_F 0.1f

// Global accumulators (zero-initialized at module load; reset by last block
// each call so graph replays stay correct).
__device__ float        g_sum;
__device__ int          g_cnt;
__device__ unsigned int g_done;

// ---------------------------------------------------------------------------
// Single fused kernel. Block b handles anchors [b*TA, b*TA+TA).
//  1. load raw anchor rows to smem, compute anchor inverse norms
//  2. stream all raw rows once: dot with TA anchors + row self-dot
//     -> sim[ar][j] = dot / (|a| |j|)   (no separate normalize pass)
//  3. triplet accumulation (semihard denominator = active count)
//  4. global atomic reduce; last block finalizes out[0] and resets state
// Labels dtype (int32 vs int64) detected at runtime.
// ---------------------------------------------------------------------------
__global__ __launch_bounds__(256) void fused_triplet_kernel(
    const float* __restrict__ emb,
    const int*   __restrict__ labels_raw,
    float*       __restrict__ out,
    int n, int nblocks) {

    __shared__ float s_anchor[TA][DDIM];
    __shared__ float s_ainv[TA];
    __shared__ float s_sim[TA][NMAX];
    __shared__ int   s_lab[NMAX];
    __shared__ int   s_pos[NMAX];
    __shared__ int   s_npos;
    __shared__ int   s_oddor;
    __shared__ float s_redf[256];
    __shared__ int   s_redi[256];

    const int t  = threadIdx.x;          // 256 threads
    const int a0 = blockIdx.x * TA;

    // --- labels dtype detection: OR of odd int32 words ---
    if (t == 0) s_oddor = 0;
    __syncthreads();
    int oddacc = 0;
    for (int j = t; j < n; j += 256)
        if (j & 1) oddacc |= labels_raw[j];
    #pragma unroll
    for (int o = 16; o > 0; o >>= 1)
        oddacc |= __shfl_xor_sync(0xffffffffu, oddacc, o);
    if ((t & 31) == 0 && oddacc) atomicOr(&s_oddor, oddacc);

    // --- anchor rows -> smem (raw) ---
    for (int i = t; i < TA * DDIM; i += 256) {
        int ar = i / DDIM, c = i % DDIM;
        int a = a0 + ar;
        s_anchor[ar][c] = (a < n) ? emb[(size_t)a * DDIM + c] : 1.0f;
    }
    __syncthreads();
    bool is_i32 = (s_oddor != 0);

    // labels -> smem
    for (int j = t; j < n; j += 256)
        s_lab[j] = is_i32 ? labels_raw[j] : labels_raw[2 * j];

    // anchor inverse norms: warp w (<TA) reduces anchor w
    {
        int w = t >> 5, lane = t & 31;
        if (w < TA) {
            float ss = 0.0f;
            #pragma unroll
            for (int k = 0; k < DDIM / 32; k++) {
                float v = s_anchor[w][lane + 32 * k];
                ss += v * v;
            }
            #pragma unroll
            for (int o = 16; o > 0; o >>= 1)
                ss += __shfl_xor_sync(0xffffffffu, ss, o);
            if (lane == 0) s_ainv[w] = 1.0f / sqrtf(ss);
        }
    }
    __syncthreads();

    // --- stream all rows: dots + self-norm in one pass ---
    float ainv[TA];
    #pragma unroll
    for (int ar = 0; ar < TA; ar++) ainv[ar] = s_ainv[ar];

    for (int j = t; j < n; j += 256) {
        const float4* row = (const float4*)(emb + (size_t)j * DDIM);
        float acc[TA];
        float ssj = 0.0f;
        #pragma unroll
        for (int ar = 0; ar < TA; ar++) acc[ar] = 0.0f;
        #pragma unroll 4
        for (int c4 = 0; c4 < DDIM / 4; c4++) {
            float4 e = row[c4];
            ssj += e.x * e.x + e.y * e.y + e.z * e.z + e.w * e.w;
            #pragma unroll
            for (int ar = 0; ar < TA; ar++) {
                float4 av = ((const float4*)s_anchor[ar])[c4];
                acc[ar] += e.x * av.x + e.y * av.y + e.z * av.z + e.w * av.w;
            }
        }
        float jinv = 1.0f / sqrtf(ssj);
        #pragma unroll
        for (int ar = 0; ar < TA; ar++)
            s_sim[ar][j] = acc[ar] * ainv[ar] * jinv;
    }
    __syncthreads();

    // --- triplet accumulation ---
    float sum = 0.0f;
    int   cnt = 0;

    for (int ar = 0; ar < TA; ar++) {
        int a = a0 + ar;
        bool valid_a = (a < n);
        int la = valid_a ? s_lab[a] : -1;

        if (t == 0) s_npos = 0;
        __syncthreads();

        if (valid_a) {
            for (int j = t; j < n; j += 256) {
                if (j != a && s_lab[j] == la) {
                    int idx = atomicAdd(&s_npos, 1);
                    s_pos[idx] = j;
                }
            }
        }
        __syncthreads();
        int npos = s_npos;

        if (valid_a && npos > 0) {
            for (int nj = t; nj < n; nj += 256) {
                if (s_lab[nj] != la) {
                    float sn = s_sim[ar][nj] + MARGIN_F;
                    for (int pi = 0; pi < npos; pi++) {
                        float v = sn - s_sim[ar][s_pos[pi]];
                        float r = fmaxf(v, 0.0f);
                        sum += r;
                        cnt += (r > 1e-16f) ? 1 : 0;
                    }
                }
            }
        }
        __syncthreads();
    }

    // --- block reduce (sum and count together) ---
    s_redf[t] = sum;
    s_redi[t] = cnt;
    __syncthreads();
    #pragma unroll
    for (int o = 128; o > 0; o >>= 1) {
        if (t < o) {
            s_redf[t] += s_redf[t + o];
            s_redi[t] += s_redi[t + o];
        }
        __syncthreads();
    }

    // --- global reduce + last-block finalize ---
    if (t == 0) {
        atomicAdd(&g_sum, s_redf[0]);
        atomicAdd(&g_cnt, s_redi[0]);
        __threadfence();
        unsigned int d = atomicAdd(&g_done, 1u);
        if (d == (unsigned int)(nblocks - 1)) {
            float fs = g_sum;
            float fc = (float)g_cnt;
            out[0] = fs / (fc + 1e-16f);
            // reset for next graph replay
            g_sum  = 0.0f;
            g_cnt  = 0;
            __threadfence();
            g_done = 0u;
        }
    }
}

extern "C" void kernel_launch(void* const* d_in, const int* in_sizes, int n_in,
                              void* d_out, int out_size) {
    const float* emb    = (const float*)d_in[0];
    const int*   labels = (const int*)d_in[1];
    float*       out    = (float*)d_out;

    int n = in_sizes[1];
    if (n > NMAX) n = NMAX;

    int nblocks = (n + TA - 1) / TA;
    fused_triplet_kernel<<<nblocks, 256>>>(emb, labels, out, n, nblocks);
}

// round 4
// speedup vs baseline: 1.2613x; 1.2613x over previous
#include <cuda_runtime.h>
#include <cuda_bf16.h>

#define NMAX 512
#define DDIM 128
#define TA 4
#define MARGIN_F 0.1f
#define TILE_ROWS 256
#define TSTRIDE 132   // floats per smem tile row: 528B (16B-aligned), bank-conflict-free

// Global accumulators (zero at load; last block resets them each call so
// graph replays stay deterministic).
__device__ float        g_sum;
__device__ int          g_cnt;
__device__ unsigned int g_done;

union U2 { unsigned long long u; float2 f; };

// Packed dual-FMA (sm_10x): d.lo += a.lo*b.lo ; d.hi += a.hi*b.hi
__device__ __forceinline__ void ffma2(unsigned long long& d,
                                      unsigned long long a,
                                      unsigned long long b) {
    asm("fma.rn.f32x2 %0, %1, %2, %0;" : "+l"(d) : "l"(a), "l"(b));
}

extern __shared__ float s_tile[];   // TILE_ROWS * TSTRIDE floats (dynamic)

__global__ __launch_bounds__(256) void fused_triplet_kernel(
    const float* __restrict__ emb,
    const int*   __restrict__ labels_raw,
    float*       __restrict__ out,
    int n, int nblocks) {

    __shared__ __align__(16) float s_anchor[TA][DDIM];
    __shared__ float s_ainv[TA];
    __shared__ float s_sim[TA][NMAX];
    __shared__ int   s_lab[NMAX];
    __shared__ int   s_pos[NMAX];
    __shared__ int   s_npos;
    __shared__ int   s_oddor;
    __shared__ float s_redf[256];
    __shared__ int   s_redi[256];

    const int t  = threadIdx.x;          // 256 threads
    const int a0 = blockIdx.x * TA;

    // --- labels dtype detection (int32 vs int64): OR of odd int32 words ---
    if (t == 0) s_oddor = 0;
    __syncthreads();
    int oddacc = 0;
    for (int j = t; j < n; j += 256)
        if (j & 1) oddacc |= labels_raw[j];
    #pragma unroll
    for (int o = 16; o > 0; o >>= 1)
        oddacc |= __shfl_xor_sync(0xffffffffu, oddacc, o);
    if ((t & 31) == 0 && oddacc) atomicOr(&s_oddor, oddacc);

    // --- anchor rows -> smem (raw values) ---
    for (int i = t; i < TA * DDIM; i += 256) {
        int ar = i / DDIM, c = i % DDIM;
        int a = a0 + ar;
        s_anchor[ar][c] = (a < n) ? emb[(size_t)a * DDIM + c] : 1.0f;
    }
    __syncthreads();
    const bool is_i32 = (s_oddor != 0);

    // labels -> smem
    for (int j = t; j < n; j += 256)
        s_lab[j] = is_i32 ? labels_raw[j] : labels_raw[2 * j];

    // anchor inverse norms: warp w (<TA) reduces anchor w
    {
        int w = t >> 5, lane = t & 31;
        if (w < TA) {
            float ss = 0.0f;
            #pragma unroll
            for (int k = 0; k < DDIM / 32; k++) {
                float v = s_anchor[w][lane + 32 * k];
                ss += v * v;
            }
            #pragma unroll
            for (int o = 16; o > 0; o >>= 1)
                ss += __shfl_xor_sync(0xffffffffu, ss, o);
            if (lane == 0) s_ainv[w] = 1.0f / sqrtf(ss);
        }
    }
    __syncthreads();

    float ainv[TA];
    #pragma unroll
    for (int ar = 0; ar < TA; ar++) ainv[ar] = s_ainv[ar];

    // --- tiled sim computation: coalesced gmem->smem, thread-per-row dots ---
    const int tiles = (n + TILE_ROWS - 1) / TILE_ROWS;
    for (int tile = 0; tile < tiles; tile++) {
        const int base = tile * TILE_ROWS;
        const int rows = min(TILE_ROWS, n - base);

        __syncthreads();   // protect s_tile reuse across iterations

        // coalesced copy: consecutive threads -> consecutive float4s
        for (int i = t; i < rows * (DDIM / 4); i += 256) {
            int r  = i >> 5;        // DDIM/4 == 32
            int c4 = i & 31;
            float4 v = ((const float4*)emb)[(size_t)(base + r) * (DDIM / 4) + c4];
            ((float4*)(s_tile + (size_t)r * TSTRIDE))[c4] = v;
        }
        __syncthreads();

        if (t < rows) {
            const ulonglong2* row = (const ulonglong2*)(s_tile + (size_t)t * TSTRIDE);
            unsigned long long acc2[TA];
            unsigned long long ss2 = 0ull;   // (0.0f, 0.0f)
            #pragma unroll
            for (int ar = 0; ar < TA; ar++) acc2[ar] = 0ull;

            #pragma unroll 8
            for (int c4 = 0; c4 < DDIM / 4; c4++) {
                ulonglong2 e = row[c4];
                ffma2(ss2, e.x, e.x);
                ffma2(ss2, e.y, e.y);
                #pragma unroll
                for (int ar = 0; ar < TA; ar++) {
                    ulonglong2 a = ((const ulonglong2*)s_anchor[ar])[c4];
                    ffma2(acc2[ar], e.x, a.x);
                    ffma2(acc2[ar], e.y, a.y);
                }
            }

            U2 s; s.u = ss2;
            float jinv = rsqrtf(s.f.x + s.f.y);
            #pragma unroll
            for (int ar = 0; ar < TA; ar++) {
                U2 d; d.u = acc2[ar];
                s_sim[ar][base + t] = (d.f.x + d.f.y) * ainv[ar] * jinv;
            }
        }
    }
    __syncthreads();

    // --- triplet accumulation ---
    float sum = 0.0f;
    int   cnt = 0;

    for (int ar = 0; ar < TA; ar++) {
        int a = a0 + ar;
        bool valid_a = (a < n);
        int la = valid_a ? s_lab[a] : -1;

        if (t == 0) s_npos = 0;
        __syncthreads();

        if (valid_a) {
            for (int j = t; j < n; j += 256) {
                if (j != a && s_lab[j] == la) {
                    int idx = atomicAdd(&s_npos, 1);
                    s_pos[idx] = j;
                }
            }
        }
        __syncthreads();
        int npos = s_npos;

        if (valid_a && npos > 0) {
            for (int nj = t; nj < n; nj += 256) {
                if (s_lab[nj] != la) {
                    float sn = s_sim[ar][nj] + MARGIN_F;
                    for (int pi = 0; pi < npos; pi++) {
                        float v = sn - s_sim[ar][s_pos[pi]];
                        float r = fmaxf(v, 0.0f);
                        sum += r;
                        cnt += (r > 1e-16f) ? 1 : 0;
                    }
                }
            }
        }
        __syncthreads();
    }

    // --- block reduce ---
    s_redf[t] = sum;
    s_redi[t] = cnt;
    __syncthreads();
    #pragma unroll
    for (int o = 128; o > 0; o >>= 1) {
        if (t < o) {
            s_redf[t] += s_redf[t + o];
            s_redi[t] += s_redi[t + o];
        }
        __syncthreads();
    }

    // --- global reduce + last-block finalize ---
    if (t == 0) {
        atomicAdd(&g_sum, s_redf[0]);
        atomicAdd(&g_cnt, s_redi[0]);
        __threadfence();
        unsigned int d = atomicAdd(&g_done, 1u);
        if (d == (unsigned int)(nblocks - 1)) {
            float fs = g_sum;
            float fc = (float)g_cnt;
            out[0] = fs / (fc + 1e-16f);
            g_sum  = 0.0f;
            g_cnt  = 0;
            __threadfence();
            g_done = 0u;
        }
    }
}

extern "C" void kernel_launch(void* const* d_in, const int* in_sizes, int n_in,
                              void* d_out, int out_size) {
    const float* emb    = (const float*)d_in[0];
    const int*   labels = (const int*)d_in[1];
    float*       out    = (float*)d_out;

    int n = in_sizes[1];
    if (n > NMAX) n = NMAX;

    const int smem_dyn = TILE_ROWS * TSTRIDE * (int)sizeof(float);  // 135168 B
    cudaFuncSetAttribute(fused_triplet_kernel,
                         cudaFuncAttributeMaxDynamicSharedMemorySize, smem_dyn);

    int nblocks = (n + TA - 1) / TA;
    fused_triplet_kernel<<<nblocks, 256, smem_dyn>>>(emb, labels, out, n, nblocks);
}